// round 11
// baseline (speedup 1.0000x reference)
#include <cuda_runtime.h>
#include <cstdint>

#define PES 15
#define DIN 18

// ---- shared memory layout (float indices) ----
#define XA_OFF   0            // X A-frag layout: 64 blks * 128 = 8192 floats (32KB)
#define W1_OFF   8192         // W1 B-frag PAIRED layout: 32 pairblks * 128 = 4096 (16KB)
#define W2_OFF   12288        // W2 B-frag PAIRED layout: 128 pairblks * 128 = 16384 (64KB)
#define B1_OFF   28672        // 128
#define B2_OFF   28800        // 128
#define W3_OFF   28928        // 384
#define B3_OFF   29312        // 4
#define PX_OFF   29316        // 256*3 = 768
#define SMEM_FLOATS 30084
#define SMEM_BYTES (SMEM_FLOATS * 4)

__device__ __forceinline__ uint32_t f2tf32(float x) {
    uint32_t r;
    asm("cvt.rna.tf32.f32 %0, %1;" : "=r"(r) : "f"(x));
    return r;
}
__device__ __forceinline__ float tf32f(float x) {
    return __uint_as_float(f2tf32(x));
}

// D += A(16x8) * B(8x8), tf32 operands, f32 accum
__device__ __forceinline__ void mma8(float* d, const uint32_t* a, const uint32_t* b) {
    asm volatile("mma.sync.aligned.m16n8k8.row.col.f32.tf32.tf32.f32 "
                 "{%0,%1,%2,%3}, {%4,%5,%6,%7}, {%8,%9}, {%0,%1,%2,%3};"
                 : "+f"(d[0]), "+f"(d[1]), "+f"(d[2]), "+f"(d[3])
                 : "r"(a[0]), "r"(a[1]), "r"(a[2]), "r"(a[3]),
                   "r"(b[0]), "r"(b[1]));
}

__global__ __launch_bounds__(256, 1)
void nsc_m32b_kernel(const float* __restrict__ points,
                     const float* __restrict__ enc,
                     const float* __restrict__ W1, const float* __restrict__ b1,
                     const float* __restrict__ W2, const float* __restrict__ b2,
                     const float* __restrict__ W3, const float* __restrict__ b3,
                     const int* __restrict__ complexes,
                     float* __restrict__ out, int C, long long lipIdx)
{
    extern __shared__ float sm[];
    uint32_t* smu = (uint32_t*)sm;

    const int tid  = threadIdx.x;
    const int lane = tid & 31;
    const int wcta = tid >> 5;        // warp id; owns rows [wcta*32, wcta*32+32)

    // ============ stage weights ONCE (persistent CTA) ============
    // PAIRED B-frag layout: pairblk = kk*8 + ntp covers nt = 2*ntp, 2*ntp+1.
    // slot = pairblk*128 + ln*4 + sub; sub: 0,1 = regs of nt_even; 2,3 = nt_odd.
    // value = W[n][k], n = nt*8 + ln/4, k = kk*8 + (ln&3) + 4*reg.
    for (int idx = tid; idx < 4096; idx += 256) {            // W1 (4 kk * 8 ntp)
        int pb = idx >> 7, r = idx & 127;
        int ln = r >> 2, sub = r & 3;
        int kk = pb >> 3, ntp = pb & 7;
        int nt = ntp * 2 + (sub >> 1), rg = sub & 1;
        int n = nt * 8 + (ln >> 2), k = kk * 8 + (ln & 3) + 4 * rg;
        float v = (k < DIN) ? __ldg(&W1[n * DIN + k]) : 0.f;
        smu[W1_OFF + idx] = f2tf32(v);
    }
    for (int idx = tid; idx < 16384; idx += 256) {           // W2 (16 kk * 8 ntp)
        int pb = idx >> 7, r = idx & 127;
        int ln = r >> 2, sub = r & 3;
        int kk = pb >> 3, ntp = pb & 7;
        int nt = ntp * 2 + (sub >> 1), rg = sub & 1;
        int n = nt * 8 + (ln >> 2), k = kk * 8 + (ln & 3) + 4 * rg;
        smu[W2_OFF + idx] = f2tf32(__ldg(&W2[n * 128 + k]));
    }
    if (tid < 128) { sm[B1_OFF + tid] = b1[tid]; sm[B2_OFF + tid] = b2[tid]; }
    for (int idx = tid; idx < 384; idx += 256) sm[W3_OFF + idx] = W3[idx];
    if (tid < 3) sm[B3_OFF + tid] = b3[tid];

    if (blockIdx.x == 0 && tid == 0) out[lipIdx] = 1.0f;

    const int src1 = (lane & ~3) | ((lane & 3) >> 1);
    const int src2 = src1 + 2;
    const bool par = (lane & 1) != 0;
    const long long xoff = (long long)C * 256 * 3;

    // ============ persistent loop: 1 tile = 1 full complex (256 rows) ============
    for (int c = blockIdx.x; c < C; c += gridDim.x) {
        __syncthreads();   // previous tile fully consumed before restaging XA/px

        // ---- features: thread t -> row t (0..255) ----
        {
            int v4[4];
            #pragma unroll
            for (int q = 0; q < 4; q++) v4[q] = complexes[c * 4 + q];

            const int gi = tid >> 4, gj = tid & 15;
            const float inv = 1.0f / 15.0f;
            const float u = gi * inv, w = gj * inv;
            float wt[4];
            wt[0] = (1.f - u) * (1.f - w); wt[1] = (1.f - u) * w;
            wt[2] = u * (1.f - w);         wt[3] = u * w;

            float xf[32];
            #pragma unroll
            for (int f = 0; f < PES; f++) {
                float s = 0.f;
                #pragma unroll
                for (int q = 0; q < 4; q++) s += wt[q] * __ldg(&enc[(long long)v4[q] * PES + f]);
                xf[f] = s;
            }
            #pragma unroll
            for (int f = 0; f < 3; f++) {
                float s = 0.f;
                #pragma unroll
                for (int q = 0; q < 4; q++) s += wt[q] * __ldg(&points[(long long)v4[q] * 3 + f]);
                sm[PX_OFF + tid * 3 + f] = s;
                xf[PES + f] = __sinf(s);
            }
            #pragma unroll
            for (int f = DIN; f < 32; f++) xf[f] = 0.f;

            // scatter into A-frag layout: block (tid>>4)*4+kk
            const int r16  = tid & 15;
            const int base = (tid >> 4) * 512 + ((r16 & 7) * 4) * 4 + (r16 >> 3);
            #pragma unroll
            for (int col = 0; col < 32; col++) {
                int kk = col >> 3, c8 = col & 7;
                smu[XA_OFF + base + kk * 128 + (c8 & 3) * 4 + ((c8 >> 2) << 1)] = f2tf32(xf[col]);
            }
        }
        __syncthreads();

        // ---- layer 1 (nt-outer, tiny live h) + sin + permute -> a2 ----
        uint4 av[2][4];                  // A-fragments, loaded once (32 regs)
        #pragma unroll
        for (int mt = 0; mt < 2; mt++)
            #pragma unroll
            for (int kk = 0; kk < 4; kk++)
                av[mt][kk] = *(const uint4*)&smu[XA_OFF + ((wcta * 2 + mt) * 4 + kk) * 128 + lane * 4];

        uint32_t a2[2][16][4];           // layer-2 A operands (128 regs)
        #pragma unroll
        for (int ntp = 0; ntp < 8; ntp++) {
            float hh[2][2][4];
            #pragma unroll
            for (int mt = 0; mt < 2; mt++)
                #pragma unroll
                for (int s = 0; s < 2; s++)
                    #pragma unroll
                    for (int r = 0; r < 4; r++) hh[mt][s][r] = 0.f;

            #pragma unroll
            for (int kk = 0; kk < 4; kk++) {
                uint4 bv = *(const uint4*)&smu[W1_OFF + (kk * 8 + ntp) * 128 + lane * 4];
                mma8(hh[0][0], (const uint32_t*)&av[0][kk], &bv.x);
                mma8(hh[0][1], (const uint32_t*)&av[0][kk], &bv.z);
                mma8(hh[1][0], (const uint32_t*)&av[1][kk], &bv.x);
                mma8(hh[1][1], (const uint32_t*)&av[1][kk], &bv.z);
            }

            #pragma unroll
            for (int s = 0; s < 2; s++) {
                int nt = ntp * 2 + s;
                float2 bb = *(const float2*)&sm[B1_OFF + nt * 8 + 2 * (lane & 3)];
                #pragma unroll
                for (int mt = 0; mt < 2; mt++) {
                    float s0 = tf32f(__sinf(hh[mt][s][0] + bb.x));
                    float s1 = tf32f(__sinf(hh[mt][s][1] + bb.y));
                    float s2 = tf32f(__sinf(hh[mt][s][2] + bb.x));
                    float s3 = tf32f(__sinf(hh[mt][s][3] + bb.y));
                    float t0 = __shfl_sync(0xffffffffu, s0, src1);
                    float t1 = __shfl_sync(0xffffffffu, s1, src1);
                    float t2 = __shfl_sync(0xffffffffu, s2, src1);
                    float t3 = __shfl_sync(0xffffffffu, s3, src1);
                    float u0 = __shfl_sync(0xffffffffu, s0, src2);
                    float u1 = __shfl_sync(0xffffffffu, s1, src2);
                    float u2 = __shfl_sync(0xffffffffu, s2, src2);
                    float u3 = __shfl_sync(0xffffffffu, s3, src2);
                    a2[mt][nt][0] = __float_as_uint(par ? t1 : t0);
                    a2[mt][nt][1] = __float_as_uint(par ? t3 : t2);
                    a2[mt][nt][2] = __float_as_uint(par ? u1 : u0);
                    a2[mt][nt][3] = __float_as_uint(par ? u3 : u2);
                }
            }
        }

        // ---- layer 2 (4 N-passes, small acc) + fused layer 3 ----
        float p3[2][2][3];
        #pragma unroll
        for (int mt = 0; mt < 2; mt++)
            #pragma unroll
            for (int rh = 0; rh < 2; rh++)
                #pragma unroll
                for (int f = 0; f < 3; f++) p3[mt][rh][f] = 0.f;

        #pragma unroll
        for (int pass = 0; pass < 4; pass++) {
            float acc[2][4][4];          // 32 regs
            #pragma unroll
            for (int mt = 0; mt < 2; mt++)
                #pragma unroll
                for (int nt = 0; nt < 4; nt++)
                    #pragma unroll
                    for (int r = 0; r < 4; r++) acc[mt][nt][r] = 0.f;

            #pragma unroll
            for (int kk = 0; kk < 16; kk++) {
                #pragma unroll
                for (int ntpl = 0; ntpl < 2; ntpl++) {
                    int ntp = pass * 2 + ntpl;
                    uint4 bv = *(const uint4*)&smu[W2_OFF + (kk * 8 + ntp) * 128 + lane * 4];
                    mma8(acc[0][2 * ntpl + 0], a2[0][kk], &bv.x);
                    mma8(acc[0][2 * ntpl + 1], a2[0][kk], &bv.z);
                    mma8(acc[1][2 * ntpl + 0], a2[1][kk], &bv.x);
                    mma8(acc[1][2 * ntpl + 1], a2[1][kk], &bv.z);
                }
            }

            // epilogue: sin(D2 + b2), accumulate layer-3 partials
            #pragma unroll
            for (int ntl = 0; ntl < 4; ntl++) {
                int nt = pass * 4 + ntl;
                float2 bb = *(const float2*)&sm[B2_OFF + nt * 8 + 2 * (lane & 3)];
                #pragma unroll
                for (int mt = 0; mt < 2; mt++) {
                    float h0 = __sinf(acc[mt][ntl][0] + bb.x);
                    float h1v = __sinf(acc[mt][ntl][1] + bb.y);
                    float h2v = __sinf(acc[mt][ntl][2] + bb.x);
                    float h3 = __sinf(acc[mt][ntl][3] + bb.y);
                    #pragma unroll
                    for (int f = 0; f < 3; f++) {
                        float2 wv = *(const float2*)&sm[W3_OFF + f * 128 + nt * 8 + 2 * (lane & 3)];
                        p3[mt][0][f] += h0 * wv.x + h1v * wv.y;
                        p3[mt][1][f] += h2v * wv.x + h3 * wv.y;
                    }
                }
            }
        }

        // reduce layer-3 partials across each quad
        #pragma unroll
        for (int mt = 0; mt < 2; mt++)
            #pragma unroll
            for (int rh = 0; rh < 2; rh++)
                #pragma unroll
                for (int f = 0; f < 3; f++) {
                    float v = p3[mt][rh][f];
                    v += __shfl_xor_sync(0xffffffffu, v, 1);
                    v += __shfl_xor_sync(0xffffffffu, v, 2);
                    p3[mt][rh][f] = v;
                }

        if ((lane & 3) == 0) {
            const int q = lane >> 2;
            #pragma unroll
            for (int mt = 0; mt < 2; mt++)
                #pragma unroll
                for (int rh = 0; rh < 2; rh++) {
                    int row = wcta * 32 + mt * 16 + rh * 8 + q;   // 0..255
                    long long g = (long long)c * 256 + row;
                    #pragma unroll
                    for (int f = 0; f < 3; f++) {
                        float o = p3[mt][rh][f] + sm[B3_OFF + f];
                        out[g * 3 + f]        = sm[PX_OFF + row * 3 + f] + o;
                        out[xoff + g * 3 + f] = o;
                    }
                }
        }
    }
}

extern "C" void kernel_launch(void* const* d_in, const int* in_sizes, int n_in,
                              void* d_out, int out_size) {
    const float* points    = (const float*)d_in[0];
    const float* enc       = (const float*)d_in[1];
    const float* W1        = (const float*)d_in[2];
    const float* b1        = (const float*)d_in[3];
    const float* W2        = (const float*)d_in[4];
    const float* b2        = (const float*)d_in[5];
    const float* W3        = (const float*)d_in[6];
    const float* b3        = (const float*)d_in[7];
    const int*   complexes = (const int*)d_in[8];   // JAX int64 -> int32 (x64 disabled)

    const int C = in_sizes[8] / 4;
    float* out = (float*)d_out;

    int grid = 148;                    // persistent: 1 CTA per SM on B200
    if (grid > C) grid = C;

    cudaFuncSetAttribute(nsc_m32b_kernel,
                         cudaFuncAttributeMaxDynamicSharedMemorySize, SMEM_BYTES);
    nsc_m32b_kernel<<<grid, 256, SMEM_BYTES>>>(points, enc, W1, b1, W2, b2, W3, b3,
                                               complexes, out, C,
                                               (long long)out_size - 1);
}

// round 12
// speedup vs baseline: 1.0328x; 1.0328x over previous
#include <cuda_runtime.h>
#include <cstdint>

#define PES 15
#define DIN 18

// ---- shared memory layout (float indices) ----
#define XA_OFF   0            // X A-frag layout: 8 warps * 4 kk * 128 = 4096 floats (16KB)
#define W1_OFF   4096         // W1 B-frag PAIRED: 4 kk * 8 ntp * 128 = 4096 (16KB)
#define W2_OFF   8192         // W2 B-frag PAIRED: 16 kk * 8 ntp * 128 = 16384 (64KB)
#define B1_OFF   24576        // 128
#define B2_OFF   24704        // 128
#define W3_OFF   24832        // 384
#define B3_OFF   25216        // 4
#define PX_OFF   25220        // 128*3 = 384
#define SMEM_FLOATS 25604
#define SMEM_BYTES (SMEM_FLOATS * 4)

__device__ __forceinline__ uint32_t f2tf32(float x) {
    uint32_t r;
    asm("cvt.rna.tf32.f32 %0, %1;" : "=r"(r) : "f"(x));
    return r;
}
__device__ __forceinline__ float tf32f(float x) {
    return __uint_as_float(f2tf32(x));
}

// D += A(16x8) * B(8x8), tf32 operands, f32 accum
__device__ __forceinline__ void mma8(float* d, const uint32_t* a, const uint32_t* b) {
    asm volatile("mma.sync.aligned.m16n8k8.row.col.f32.tf32.tf32.f32 "
                 "{%0,%1,%2,%3}, {%4,%5,%6,%7}, {%8,%9}, {%0,%1,%2,%3};"
                 : "+f"(d[0]), "+f"(d[1]), "+f"(d[2]), "+f"(d[3])
                 : "r"(a[0]), "r"(a[1]), "r"(a[2]), "r"(a[3]),
                   "r"(b[0]), "r"(b[1]));
}

__global__ __launch_bounds__(256, 2)
void nsc_p16_kernel(const float* __restrict__ points,
                    const float* __restrict__ enc,
                    const float* __restrict__ W1, const float* __restrict__ b1,
                    const float* __restrict__ W2, const float* __restrict__ b2,
                    const float* __restrict__ W3, const float* __restrict__ b3,
                    const int* __restrict__ complexes,
                    float* __restrict__ out, int C, long long lipIdx)
{
    extern __shared__ float sm[];
    uint32_t* smu = (uint32_t*)sm;

    const int tid  = threadIdx.x;
    const int lane = tid & 31;
    const int wcta = tid >> 5;        // warp id; owns rows [wcta*16, wcta*16+16)

    // ============ stage weights ONCE (persistent CTA) ============
    // PAIRED B-frag layout: pairblk = kk*8 + ntp covers nt = 2*ntp, 2*ntp+1.
    // slot = pairblk*128 + ln*4 + sub; sub 0,1 = regs of nt_even; 2,3 = nt_odd.
    // value = W[n][k], n = nt*8 + ln/4, k = kk*8 + (ln&3) + 4*reg.
    for (int idx = tid; idx < 4096; idx += 256) {            // W1 (4 kk * 8 ntp)
        int pb = idx >> 7, r = idx & 127;
        int ln = r >> 2, sub = r & 3;
        int kk = pb >> 3, ntp = pb & 7;
        int nt = ntp * 2 + (sub >> 1), rg = sub & 1;
        int n = nt * 8 + (ln >> 2), k = kk * 8 + (ln & 3) + 4 * rg;
        float v = (k < DIN) ? __ldg(&W1[n * DIN + k]) : 0.f;
        smu[W1_OFF + idx] = f2tf32(v);
    }
    for (int idx = tid; idx < 16384; idx += 256) {           // W2 (16 kk * 8 ntp)
        int pb = idx >> 7, r = idx & 127;
        int ln = r >> 2, sub = r & 3;
        int kk = pb >> 3, ntp = pb & 7;
        int nt = ntp * 2 + (sub >> 1), rg = sub & 1;
        int n = nt * 8 + (ln >> 2), k = kk * 8 + (ln & 3) + 4 * rg;
        smu[W2_OFF + idx] = f2tf32(__ldg(&W2[n * 128 + k]));
    }
    if (tid < 128) { sm[B1_OFF + tid] = b1[tid]; sm[B2_OFF + tid] = b2[tid]; }
    for (int idx = tid; idx < 384; idx += 256) sm[W3_OFF + idx] = W3[idx];
    if (tid < 3) sm[B3_OFF + tid] = b3[tid];

    if (blockIdx.x == 0 && tid == 0) out[lipIdx] = 1.0f;

    const int src1 = (lane & ~3) | ((lane & 3) >> 1);
    const int src2 = src1 + 2;
    const bool par = (lane & 1) != 0;
    const long long xoff = (long long)C * 256 * 3;
    const int total = 2 * C;

    // ============ persistent loop over half-complexes ============
    for (int b = blockIdx.x; b < total; b += gridDim.x) {
        const int c    = b >> 1;
        const int half = b & 1;

        __syncthreads();   // previous tile fully consumed before restaging XA/px

        // ---- features: thread t (<128) -> local row t ----
        if (tid < 128) {
            int v4[4];
            #pragma unroll
            for (int q = 0; q < 4; q++) v4[q] = complexes[c * 4 + q];

            const int p_idx = half * 128 + tid;       // 0..255 within complex
            const int gi = p_idx >> 4, gj = p_idx & 15;
            const float inv = 1.0f / 15.0f;
            const float u = gi * inv, w = gj * inv;
            float wt[4];
            wt[0] = (1.f - u) * (1.f - w); wt[1] = (1.f - u) * w;
            wt[2] = u * (1.f - w);         wt[3] = u * w;

            float xf[32];
            #pragma unroll
            for (int f = 0; f < PES; f++) {
                float s = 0.f;
                #pragma unroll
                for (int q = 0; q < 4; q++) s += wt[q] * __ldg(&enc[(long long)v4[q] * PES + f]);
                xf[f] = s;
            }
            #pragma unroll
            for (int f = 0; f < 3; f++) {
                float s = 0.f;
                #pragma unroll
                for (int q = 0; q < 4; q++) s += wt[q] * __ldg(&points[(long long)v4[q] * 3 + f]);
                sm[PX_OFF + tid * 3 + f] = s;
                xf[PES + f] = __sinf(s);
            }
            #pragma unroll
            for (int f = DIN; f < 32; f++) xf[f] = 0.f;

            // scatter into A-frag layout for dest warp (tid>>4)
            const int r16  = tid & 15;
            const int base = (tid >> 4) * 512 + ((r16 & 7) * 4) * 4 + (r16 >> 3);
            #pragma unroll
            for (int col = 0; col < 32; col++) {
                int kk = col >> 3, c8 = col & 7;
                smu[XA_OFF + base + kk * 128 + (c8 & 3) * 4 + ((c8 >> 2) << 1)] = f2tf32(xf[col]);
            }
        }
        __syncthreads();

        // ---- layer 1: X[16x32] @ W1^T -> h[16][4] (paired B loads) ----
        float h[16][4];
        #pragma unroll
        for (int nt = 0; nt < 16; nt++)
            #pragma unroll
            for (int r = 0; r < 4; r++) h[nt][r] = 0.f;

        #pragma unroll
        for (int kk = 0; kk < 4; kk++) {
            uint4 av = *(const uint4*)&smu[XA_OFF + (wcta * 4 + kk) * 128 + lane * 4];
            #pragma unroll
            for (int ntp = 0; ntp < 8; ntp++) {
                uint4 bv = *(const uint4*)&smu[W1_OFF + (kk * 8 + ntp) * 128 + lane * 4];
                mma8(h[2 * ntp + 0], (const uint32_t*)&av, &bv.x);
                mma8(h[2 * ntp + 1], (const uint32_t*)&av, &bv.z);
            }
        }

        // sin(D1 + b1) -> tf32, permute into layer-2 A-frags a2[16][4]
        uint32_t a2[16][4];
        #pragma unroll
        for (int kk = 0; kk < 16; kk++) {
            float2 bb = *(const float2*)&sm[B1_OFF + kk * 8 + 2 * (lane & 3)];
            float s0 = tf32f(__sinf(h[kk][0] + bb.x));
            float s1 = tf32f(__sinf(h[kk][1] + bb.y));
            float s2 = tf32f(__sinf(h[kk][2] + bb.x));
            float s3 = tf32f(__sinf(h[kk][3] + bb.y));
            float t0 = __shfl_sync(0xffffffffu, s0, src1);
            float t1 = __shfl_sync(0xffffffffu, s1, src1);
            float t2 = __shfl_sync(0xffffffffu, s2, src1);
            float t3 = __shfl_sync(0xffffffffu, s3, src1);
            float u0 = __shfl_sync(0xffffffffu, s0, src2);
            float u1 = __shfl_sync(0xffffffffu, s1, src2);
            float u2 = __shfl_sync(0xffffffffu, s2, src2);
            float u3 = __shfl_sync(0xffffffffu, s3, src2);
            a2[kk][0] = __float_as_uint(par ? t1 : t0);
            a2[kk][1] = __float_as_uint(par ? t3 : t2);
            a2[kk][2] = __float_as_uint(par ? u1 : u0);
            a2[kk][3] = __float_as_uint(par ? u3 : u2);
        }

        // ---- layer 2 (2 N-passes, paired B loads) + fused layer 3 ----
        float p3[2][3];
        #pragma unroll
        for (int rh = 0; rh < 2; rh++)
            #pragma unroll
            for (int f = 0; f < 3; f++) p3[rh][f] = 0.f;

        #pragma unroll
        for (int pass = 0; pass < 2; pass++) {
            float acc[8][4];
            #pragma unroll
            for (int nt = 0; nt < 8; nt++)
                #pragma unroll
                for (int r = 0; r < 4; r++) acc[nt][r] = 0.f;

            #pragma unroll
            for (int kk = 0; kk < 16; kk++) {
                #pragma unroll
                for (int ntpl = 0; ntpl < 4; ntpl++) {
                    int ntp = pass * 4 + ntpl;
                    uint4 bv = *(const uint4*)&smu[W2_OFF + (kk * 8 + ntp) * 128 + lane * 4];
                    mma8(acc[2 * ntpl + 0], a2[kk], &bv.x);
                    mma8(acc[2 * ntpl + 1], a2[kk], &bv.z);
                }
            }

            // epilogue: sin(D2 + b2), accumulate layer-3 partials
            #pragma unroll
            for (int ntl = 0; ntl < 8; ntl++) {
                int nt = pass * 8 + ntl;
                float2 bb = *(const float2*)&sm[B2_OFF + nt * 8 + 2 * (lane & 3)];
                float h0 = __sinf(acc[ntl][0] + bb.x);
                float h1v = __sinf(acc[ntl][1] + bb.y);
                float h2v = __sinf(acc[ntl][2] + bb.x);
                float h3 = __sinf(acc[ntl][3] + bb.y);
                #pragma unroll
                for (int f = 0; f < 3; f++) {
                    float2 wv = *(const float2*)&sm[W3_OFF + f * 128 + nt * 8 + 2 * (lane & 3)];
                    p3[0][f] += h0 * wv.x + h1v * wv.y;
                    p3[1][f] += h2v * wv.x + h3 * wv.y;
                }
            }
        }

        // reduce layer-3 partials across each quad
        #pragma unroll
        for (int rh = 0; rh < 2; rh++)
            #pragma unroll
            for (int f = 0; f < 3; f++) {
                float v = p3[rh][f];
                v += __shfl_xor_sync(0xffffffffu, v, 1);
                v += __shfl_xor_sync(0xffffffffu, v, 2);
                p3[rh][f] = v;
            }

        if ((lane & 3) == 0) {
            const int q = lane >> 2;
            #pragma unroll
            for (int rh = 0; rh < 2; rh++) {
                int row = wcta * 16 + rh * 8 + q;            // local row (0..127)
                long long g = (long long)c * 256 + half * 128 + row;
                #pragma unroll
                for (int f = 0; f < 3; f++) {
                    float o = p3[rh][f] + sm[B3_OFF + f];
                    out[g * 3 + f]        = sm[PX_OFF + row * 3 + f] + o;
                    out[xoff + g * 3 + f] = o;
                }
            }
        }
    }
}

extern "C" void kernel_launch(void* const* d_in, const int* in_sizes, int n_in,
                              void* d_out, int out_size) {
    const float* points    = (const float*)d_in[0];
    const float* enc       = (const float*)d_in[1];
    const float* W1        = (const float*)d_in[2];
    const float* b1        = (const float*)d_in[3];
    const float* W2        = (const float*)d_in[4];
    const float* b2        = (const float*)d_in[5];
    const float* W3        = (const float*)d_in[6];
    const float* b3        = (const float*)d_in[7];
    const int*   complexes = (const int*)d_in[8];   // JAX int64 -> int32 (x64 disabled)

    const int C = in_sizes[8] / 4;
    float* out = (float*)d_out;

    int grid = 2 * 148;                // persistent: 2 CTAs per SM on B200
    if (grid > 2 * C) grid = 2 * C;

    cudaFuncSetAttribute(nsc_p16_kernel,
                         cudaFuncAttributeMaxDynamicSharedMemorySize, SMEM_BYTES);
    nsc_p16_kernel<<<grid, 256, SMEM_BYTES>>>(points, enc, W1, b1, W2, b2, W3, b3,
                                              complexes, out, C,
                                              (long long)out_size - 1);
}